// round 13
// baseline (speedup 1.0000x reference)
#include <cuda_runtime.h>
#include <cuda_fp16.h>
#include <cstdint>

#define TOKENS 2048
#define HIDDEN 4096
#define OUTDIM 4096
#define NLORA  16
#define RANK   16
#define KEXT   (HIDDEN + NLORA * RANK)   // 4352
#define KG     (KEXT / 16)               // 272 16-col groups per row

#define BM 256
#define BN 128
#define BK 128
#define NCH (KEXT / BK)                  // 34

#define STRIDE 272                       // 256B data + 16B pad (conflict-free ldmatrix)
#define OFF_A 0
#define OFF_B (BM * STRIDE)              // 69632 == 256*STRIDE -> loc = row*STRIDE uniformly
#define STG   ((BM + BN) * STRIDE)       // 104448
#define SMEM_BYTES (2 * STG)             // 208896

static_assert(KEXT % BK == 0, "");

// unified fp16 operand buffer: x rows [0, TOKENS), w rows [TOKENS, TOKENS+OUTDIM)
__device__ __align__(16) __half g_xw[(size_t)(TOKENS + OUTDIM) * KEXT];
__device__ int g_idx64;

// ---------------- helpers ----------------
__device__ __forceinline__ uint32_t smem_u32(const void* p) {
    uint32_t a;
    asm("{ .reg .u64 t; cvta.to.shared.u64 t, %1; cvt.u32.u64 %0, t; }" : "=r"(a) : "l"(p));
    return a;
}
__device__ __forceinline__ void cp16(uint32_t sdst, const void* gsrc) {
    asm volatile("cp.async.cg.shared.global [%0], [%1], 16;" :: "r"(sdst), "l"(gsrc) : "memory");
}
#define CP_COMMIT() asm volatile("cp.async.commit_group;" ::: "memory")

#define LDSM4(r, a) \
    asm volatile("ldmatrix.sync.aligned.m8n8.x4.shared.b16 {%0,%1,%2,%3}, [%4];" \
        : "=r"((r)[0]), "=r"((r)[1]), "=r"((r)[2]), "=r"((r)[3]) : "r"(a))

__device__ __forceinline__ void mma16816(float* c, const uint32_t* a, uint32_t b0, uint32_t b1) {
    asm volatile(
        "mma.sync.aligned.m16n8k16.row.col.f32.f16.f16.f32 "
        "{%0,%1,%2,%3}, {%4,%5,%6,%7}, {%8,%9}, {%0,%1,%2,%3};"
        : "+f"(c[0]), "+f"(c[1]), "+f"(c[2]), "+f"(c[3])
        : "r"(a[0]), "r"(a[1]), "r"(a[2]), "r"(a[3]), "r"(b0), "r"(b1));
}

// ---------------- prep: fused dtype-detect + x/W/lora_b -> fp16 ----------------
// block 0 additionally detects int32 vs int64 indices (all-zero odd words => int64).
__global__ void convert_all_kernel(const float* __restrict__ x,
                                   const float* __restrict__ w,
                                   const float* __restrict__ lb,
                                   const int* __restrict__ idx32) {
    if (blockIdx.x == 0) {
        __shared__ int any;
        if (threadIdx.x == 0) any = 0;
        __syncthreads();
        for (int i = threadIdx.x * 2 + 1; i < TOKENS; i += 2 * blockDim.x)
            if (idx32[i] != 0) any = 1;
        __syncthreads();
        if (threadIdx.x == 0) g_idx64 = (any == 0) ? 1 : 0;
    }

    int i = blockIdx.x * blockDim.x + threadIdx.x;   // one 16-col group
    if (i >= (TOKENS + OUTDIM) * KG) return;
    int row = i / KG;
    int c = (i % KG) * 16;

    __half h[16];
    const float4* src = nullptr;
    if (row < TOKENS) {                               // x side
        if (c < HIDDEN) src = reinterpret_cast<const float4*>(x + (size_t)row * HIDDEN + c);
    } else {                                          // w side
        int wrow = row - TOKENS;
        if (c < HIDDEN) {
            src = reinterpret_cast<const float4*>(w + (size_t)wrow * HIDDEN + c);
        } else {
            int l = (c - HIDDEN) >> 4;                // full rank-16 row of lora l
            src = reinterpret_cast<const float4*>(lb + ((size_t)l * OUTDIM + wrow) * RANK);
        }
    }
    if (src) {
#pragma unroll
        for (int g = 0; g < 4; g++) {
            float4 v = src[g];
            h[g * 4 + 0] = __float2half(v.x); h[g * 4 + 1] = __float2half(v.y);
            h[g * 4 + 2] = __float2half(v.z); h[g * 4 + 3] = __float2half(v.w);
        }
    } else {
#pragma unroll
        for (int j = 0; j < 16; j++) h[j] = __float2half(0.f);
    }
    int4* dst = reinterpret_cast<int4*>(g_xw + (size_t)row * KEXT + c);
    dst[0] = reinterpret_cast<int4*>(h)[0];
    dst[1] = reinterpret_cast<int4*>(h)[1];
}

// ---------------- prep: per-token rank-16 projection -> scattered ext cols ----------------
__global__ void lora_proj_kernel(const float* __restrict__ x,
                                 const float* __restrict__ la,
                                 const void* __restrict__ idx_raw) {
    const int t = blockIdx.x;
    int idx;
    if (g_idx64) idx = (int)((const long long*)idx_raw)[t];
    else         idx = ((const int*)idx_raw)[t];
    if (idx < 0 || idx >= NLORA) return;

    const float4* xr = reinterpret_cast<const float4*>(x + (size_t)t * HIDDEN);
    const float* A = la + (size_t)idx * RANK * HIDDEN;
    float acc[RANK];
#pragma unroll
    for (int r = 0; r < RANK; r++) acc[r] = 0.f;
    for (int j = threadIdx.x; j < HIDDEN / 4; j += 128) {
        float4 xv = xr[j];
#pragma unroll
        for (int r = 0; r < RANK; r++) {
            float4 av = reinterpret_cast<const float4*>(A + (size_t)r * HIDDEN)[j];
            acc[r] += xv.x * av.x + xv.y * av.y + xv.z * av.z + xv.w * av.w;
        }
    }
#pragma unroll
    for (int r = 0; r < RANK; r++)
#pragma unroll
        for (int o = 16; o > 0; o >>= 1)
            acc[r] += __shfl_xor_sync(0xffffffffu, acc[r], o);

    __shared__ float red[4][RANK];
    int w = threadIdx.x >> 5, l = threadIdx.x & 31;
    if (l == 0)
#pragma unroll
        for (int r = 0; r < RANK; r++) red[w][r] = acc[r];
    __syncthreads();
    if (threadIdx.x < RANK) {
        int r = threadIdx.x;
        float s = red[0][r] + red[1][r] + red[2][r] + red[3][r];
        g_xw[(size_t)t * KEXT + HIDDEN + idx * RANK + r] = __float2half(s);
    }
}

// ---------------- main GEMM: out = x_f16 @ w_f16^T (fp32 accum) + bias ----------------
__global__ void __launch_bounds__(512, 1)
gemm_kernel(const float* __restrict__ bias, float* __restrict__ out) {
    extern __shared__ char smem[];
    const uint32_t sb = smem_u32(smem);
    const int tid = threadIdx.x;
    const int lane = tid & 31, wid = tid >> 5;
    const int wm = wid >> 2, wn = wid & 3;          // 4 x 4 warps, warp tile 64 x 32
    const int m0 = (int)(blockIdx.x & 7) * BM;
    const int n0 = (int)(blockIdx.x >> 3) * BN;

    // cp.async: 384 rows x 16 segs (16B) per chunk; thread owns rows r0+32j, seg fixed
    const int r0 = tid >> 4;                         // 0..31
    const uint32_t sbase = (uint32_t)r0 * STRIDE + (uint32_t)(tid & 15) * 16;
    const uint32_t gx0 = (uint32_t)(m0 + r0) * KEXT + (uint32_t)(tid & 15) * 8;
    const uint32_t gw0 = (uint32_t)(TOKENS + n0 + r0) * KEXT + (uint32_t)(tid & 15) * 8;
    const uint32_t sstep = 32u * STRIDE;
    const uint32_t gstep = 32u * KEXT;

    // ldmatrix lane base offsets (within a stage)
    const uint32_t a_base = (uint32_t)(wm * 64 + (lane & 15)) * STRIDE + ((lane >> 4) << 4);
    const uint32_t b_base = (uint32_t)(wn * 32 + (lane & 15)) * STRIDE + ((lane >> 4) << 4);

    float acc[4][4][4];
#pragma unroll
    for (int a = 0; a < 4; a++)
#pragma unroll
        for (int b = 0; b < 4; b++)
#pragma unroll
            for (int c = 0; c < 4; c++) acc[a][b][c] = 0.f;

    // prologue: chunks 0 and 1 into stages 0 and 1
#pragma unroll
    for (int p = 0; p < 2; p++) {
        const uint32_t s0 = sb + (uint32_t)p * STG;
        const uint32_t kadd = (uint32_t)p * BK;
#pragma unroll
        for (int j = 0; j < 8; j++)
            cp16(s0 + sbase + j * sstep, g_xw + gx0 + j * gstep + kadd);
#pragma unroll
        for (int j = 0; j < 4; j++)
            cp16(s0 + sbase + (j + 8) * sstep, g_xw + gw0 + j * gstep + kadd);
        CP_COMMIT();
    }

#pragma unroll 1
    for (int ks = 0; ks < NCH; ks++) {
        const uint32_t s0 = sb + (uint32_t)(ks & 1) * STG;
        if (ks < NCH - 1) asm volatile("cp.async.wait_group 1;" ::: "memory");
        else              asm volatile("cp.async.wait_group 0;" ::: "memory");
        __syncthreads();

#pragma unroll
        for (int k16 = 0; k16 < 8; k16++) {
            const uint32_t koff = (uint32_t)k16 * 32;
            uint32_t bh[8];
            LDSM4(bh + 0, s0 + OFF_B + b_base + koff);
            LDSM4(bh + 4, s0 + OFF_B + b_base + 16 * STRIDE + koff);
#pragma unroll
            for (int mt = 0; mt < 4; mt++) {
                uint32_t ah[4];
                LDSM4(ah, s0 + OFF_A + a_base + (uint32_t)mt * 16 * STRIDE + koff);
#pragma unroll
                for (int j = 0; j < 4; j++) {
                    const int g = (j >> 1) * 4 + (j & 1);
                    mma16816(acc[mt][j], ah, bh[g], bh[g + 2]);
                }
            }
        }

        if (ks + 2 < NCH) {
            __syncthreads();                          // all reads of s0 done
            const uint32_t kadd = (uint32_t)(ks + 2) * BK;
#pragma unroll
            for (int j = 0; j < 8; j++)
                cp16(s0 + sbase + j * sstep, g_xw + gx0 + j * gstep + kadd);
#pragma unroll
            for (int j = 0; j < 4; j++)
                cp16(s0 + sbase + (j + 8) * sstep, g_xw + gw0 + j * gstep + kadd);
            CP_COMMIT();
        }
    }

    // epilogue: acc + bias -> out
    const int orow = m0 + wm * 64 + (lane >> 2);
    const int ocol = n0 + wn * 32 + (lane & 3) * 2;
#pragma unroll
    for (int mt = 0; mt < 4; mt++) {
#pragma unroll
        for (int j = 0; j < 4; j++) {
            const int r0o = orow + mt * 16;
            const int c = ocol + j * 8;
            float2 bv = *reinterpret_cast<const float2*>(bias + c);
            float2 v0, v1;
            v0.x = acc[mt][j][0] + bv.x; v0.y = acc[mt][j][1] + bv.y;
            v1.x = acc[mt][j][2] + bv.x; v1.y = acc[mt][j][3] + bv.y;
            *reinterpret_cast<float2*>(out + (size_t)r0o * OUTDIM + c) = v0;
            *reinterpret_cast<float2*>(out + (size_t)(r0o + 8) * OUTDIM + c) = v1;
        }
    }
}

// ---------------- launch ----------------
extern "C" void kernel_launch(void* const* d_in, const int* in_sizes, int n_in,
                              void* d_out, int out_size) {
    const float* x      = (const float*)d_in[0];
    const float* weight = (const float*)d_in[1];
    const float* bias   = (const float*)d_in[2];
    const float* lora_a = (const float*)d_in[3];
    const float* lora_b = (const float*)d_in[4];
    const void*  indices = d_in[5];
    float* out = (float*)d_out;

    cudaFuncSetAttribute(gemm_kernel, cudaFuncAttributeMaxDynamicSharedMemorySize, SMEM_BYTES);

    convert_all_kernel<<<((TOKENS + OUTDIM) * KG) / 256, 256>>>(x, weight, lora_b,
                                                                (const int*)indices);
    lora_proj_kernel<<<TOKENS, 128>>>(x, lora_a, indices);
    gemm_kernel<<<(TOKENS / BM) * (OUTDIM / BN), 512, SMEM_BYTES>>>(bias, out);
}

// round 14
// speedup vs baseline: 1.0473x; 1.0473x over previous
#include <cuda_runtime.h>
#include <cuda_fp16.h>
#include <cstdint>

#define TOKENS 2048
#define HIDDEN 4096
#define OUTDIM 4096
#define NLORA  16
#define RANK   16
#define KEXT   (HIDDEN + NLORA * RANK)   // 4352
#define KG     (KEXT / 16)               // 272

#define BM 256
#define BN 128
#define BK 64
#define NCH (KEXT / BK)                  // 68

#define STRIDE 144                       // 128B data + 16B pad
#define OFF_A 0
#define OFF_B (BM * STRIDE)              // 36864
#define STG   ((BM + BN) * STRIDE)       // 55296
#define SMEM_BYTES (3 * STG)             // 165888

static_assert(KEXT % BK == 0, "");

// unified fp16 operand buffer: x rows [0, TOKENS), w rows [TOKENS, TOKENS+OUTDIM)
__device__ __align__(16) __half g_xw[(size_t)(TOKENS + OUTDIM) * KEXT];
__device__ int g_idx64;

// ---------------- helpers ----------------
__device__ __forceinline__ uint32_t smem_u32(const void* p) {
    uint32_t a;
    asm("{ .reg .u64 t; cvta.to.shared.u64 t, %1; cvt.u32.u64 %0, t; }" : "=r"(a) : "l"(p));
    return a;
}
__device__ __forceinline__ void cp16(uint32_t sdst, const void* gsrc) {
    asm volatile("cp.async.cg.shared.global [%0], [%1], 16;" :: "r"(sdst), "l"(gsrc) : "memory");
}
#define CP_COMMIT() asm volatile("cp.async.commit_group;" ::: "memory")

#define LDSM4(r, a) \
    asm volatile("ldmatrix.sync.aligned.m8n8.x4.shared.b16 {%0,%1,%2,%3}, [%4];" \
        : "=r"((r)[0]), "=r"((r)[1]), "=r"((r)[2]), "=r"((r)[3]) : "r"(a))

__device__ __forceinline__ void mma16816(float* c, const uint32_t* a, uint32_t b0, uint32_t b1) {
    asm volatile(
        "mma.sync.aligned.m16n8k16.row.col.f32.f16.f16.f32 "
        "{%0,%1,%2,%3}, {%4,%5,%6,%7}, {%8,%9}, {%0,%1,%2,%3};"
        : "+f"(c[0]), "+f"(c[1]), "+f"(c[2]), "+f"(c[3])
        : "r"(a[0]), "r"(a[1]), "r"(a[2]), "r"(a[3]), "r"(b0), "r"(b1));
}

// ---------------- prep: fused dtype-detect + x/W/lora_b -> fp16 ----------------
__global__ void convert_all_kernel(const float* __restrict__ x,
                                   const float* __restrict__ w,
                                   const float* __restrict__ lb,
                                   const int* __restrict__ idx32) {
    if (blockIdx.x == 0) {
        __shared__ int any;
        if (threadIdx.x == 0) any = 0;
        __syncthreads();
        for (int i = threadIdx.x * 2 + 1; i < TOKENS; i += 2 * blockDim.x)
            if (idx32[i] != 0) any = 1;
        __syncthreads();
        if (threadIdx.x == 0) g_idx64 = (any == 0) ? 1 : 0;
    }

    int i = blockIdx.x * blockDim.x + threadIdx.x;   // one 16-col group
    if (i >= (TOKENS + OUTDIM) * KG) return;
    int row = i / KG;
    int c = (i % KG) * 16;

    __half h[16];
    const float4* src = nullptr;
    if (row < TOKENS) {                               // x side
        if (c < HIDDEN) src = reinterpret_cast<const float4*>(x + (size_t)row * HIDDEN + c);
    } else {                                          // w side
        int wrow = row - TOKENS;
        if (c < HIDDEN) {
            src = reinterpret_cast<const float4*>(w + (size_t)wrow * HIDDEN + c);
        } else {
            int l = (c - HIDDEN) >> 4;                // full rank-16 row of lora l
            src = reinterpret_cast<const float4*>(lb + ((size_t)l * OUTDIM + wrow) * RANK);
        }
    }
    if (src) {
#pragma unroll
        for (int g = 0; g < 4; g++) {
            float4 v = src[g];
            h[g * 4 + 0] = __float2half(v.x); h[g * 4 + 1] = __float2half(v.y);
            h[g * 4 + 2] = __float2half(v.z); h[g * 4 + 3] = __float2half(v.w);
        }
    } else {
#pragma unroll
        for (int j = 0; j < 16; j++) h[j] = __float2half(0.f);
    }
    int4* dst = reinterpret_cast<int4*>(g_xw + (size_t)row * KEXT + c);
    dst[0] = reinterpret_cast<int4*>(h)[0];
    dst[1] = reinterpret_cast<int4*>(h)[1];
}

// ---------------- prep: per-token rank-16 projection -> scattered ext cols ----------------
__global__ void lora_proj_kernel(const float* __restrict__ x,
                                 const float* __restrict__ la,
                                 const void* __restrict__ idx_raw) {
    const int t = blockIdx.x;
    int idx;
    if (g_idx64) idx = (int)((const long long*)idx_raw)[t];
    else         idx = ((const int*)idx_raw)[t];
    if (idx < 0 || idx >= NLORA) return;

    const float4* xr = reinterpret_cast<const float4*>(x + (size_t)t * HIDDEN);
    const float* A = la + (size_t)idx * RANK * HIDDEN;
    float acc[RANK];
#pragma unroll
    for (int r = 0; r < RANK; r++) acc[r] = 0.f;
    for (int j = threadIdx.x; j < HIDDEN / 4; j += 128) {
        float4 xv = xr[j];
#pragma unroll
        for (int r = 0; r < RANK; r++) {
            float4 av = reinterpret_cast<const float4*>(A + (size_t)r * HIDDEN)[j];
            acc[r] += xv.x * av.x + xv.y * av.y + xv.z * av.z + xv.w * av.w;
        }
    }
#pragma unroll
    for (int r = 0; r < RANK; r++)
#pragma unroll
        for (int o = 16; o > 0; o >>= 1)
            acc[r] += __shfl_xor_sync(0xffffffffu, acc[r], o);

    __shared__ float red[4][RANK];
    int w = threadIdx.x >> 5, l = threadIdx.x & 31;
    if (l == 0)
#pragma unroll
        for (int r = 0; r < RANK; r++) red[w][r] = acc[r];
    __syncthreads();
    if (threadIdx.x < RANK) {
        int r = threadIdx.x;
        float s = red[0][r] + red[1][r] + red[2][r] + red[3][r];
        g_xw[(size_t)t * KEXT + HIDDEN + idx * RANK + r] = __float2half(s);
    }
}

// ---------------- main GEMM: out = x_f16 @ w_f16^T (fp32 accum) + bias ----------------
__global__ void __launch_bounds__(512, 1)
gemm_kernel(const float* __restrict__ bias, float* __restrict__ out) {
    extern __shared__ char smem[];
    const uint32_t sb = smem_u32(smem);
    const int tid = threadIdx.x;
    const int lane = tid & 31, wid = tid >> 5;
    const int wm = wid >> 2, wn = wid & 3;          // 4 x 4 warps, warp tile 64 x 32
    const int m0 = (int)(blockIdx.x & 7) * BM;
    const int n0 = (int)(blockIdx.x >> 3) * BN;

    // cp.async slots: 384 rows x 8 segs = 3072 / 512 threads = 6 each
    uint32_t goff[6], soff[6];
#pragma unroll
    for (int j = 0; j < 6; j++) {
        int s = tid + j * 512;
        int row = s >> 3, seg = s & 7;
        uint32_t loc, grow;
        if (row < 256) { grow = m0 + row;                 loc = OFF_A + row * STRIDE; }
        else           { grow = TOKENS + n0 + row - 256;  loc = OFF_B + (row - 256) * STRIDE; }
        goff[j] = grow * (uint32_t)KEXT + (uint32_t)seg * 8;
        soff[j] = loc + (uint32_t)seg * 16;
    }

    // ldmatrix lane base offsets (within a stage)
    const uint32_t a_base = (uint32_t)(wm * 64 + (lane & 15)) * STRIDE + ((lane >> 4) << 4);
    const uint32_t b_base = (uint32_t)(wn * 32 + (lane & 15)) * STRIDE + ((lane >> 4) << 4);

    float acc[4][4][4];
#pragma unroll
    for (int a = 0; a < 4; a++)
#pragma unroll
        for (int b = 0; b < 4; b++)
#pragma unroll
            for (int c = 0; c < 4; c++) acc[a][b][c] = 0.f;

    // prologue: stages 0 and 1
#pragma unroll
    for (int p = 0; p < 2; p++) {
        uint32_t s0 = sb + (uint32_t)p * STG;
#pragma unroll
        for (int j = 0; j < 6; j++)
            cp16(s0 + soff[j], g_xw + goff[j] + p * BK);
        CP_COMMIT();
    }

#pragma unroll 1
    for (int ks = 0; ks < NCH; ks++) {
        const uint32_t s0 = sb + (uint32_t)(ks % 3) * STG;
        if (ks < NCH - 1) asm volatile("cp.async.wait_group 1;" ::: "memory");
        else              asm volatile("cp.async.wait_group 0;" ::: "memory");
        __syncthreads();

        if (ks + 2 < NCH) {
            const uint32_t sl = sb + (uint32_t)((ks + 2) % 3) * STG;
            const uint32_t kadd = (uint32_t)(ks + 2) * BK;
#pragma unroll
            for (int j = 0; j < 6; j++)
                cp16(sl + soff[j], g_xw + goff[j] + kadd);
            CP_COMMIT();
        }

#pragma unroll
        for (int k16 = 0; k16 < 4; k16++) {
            const uint32_t koff = (uint32_t)k16 * 32;
            uint32_t bh[8];
            LDSM4(bh + 0, s0 + OFF_B + b_base + koff);
            LDSM4(bh + 4, s0 + OFF_B + b_base + 16 * STRIDE + koff);
#pragma unroll
            for (int mt = 0; mt < 4; mt++) {
                uint32_t ah[4];
                LDSM4(ah, s0 + OFF_A + a_base + (uint32_t)mt * 16 * STRIDE + koff);
#pragma unroll
                for (int j = 0; j < 4; j++) {
                    const int g = (j >> 1) * 4 + (j & 1);
                    mma16816(acc[mt][j], ah, bh[g], bh[g + 2]);
                }
            }
        }
    }

    // epilogue: acc + bias -> out
    const int orow = m0 + wm * 64 + (lane >> 2);
    const int ocol = n0 + wn * 32 + (lane & 3) * 2;
#pragma unroll
    for (int mt = 0; mt < 4; mt++) {
#pragma unroll
        for (int j = 0; j < 4; j++) {
            const int r0 = orow + mt * 16;
            const int c = ocol + j * 8;
            float2 bv = *reinterpret_cast<const float2*>(bias + c);
            float2 v0, v1;
            v0.x = acc[mt][j][0] + bv.x; v0.y = acc[mt][j][1] + bv.y;
            v1.x = acc[mt][j][2] + bv.x; v1.y = acc[mt][j][3] + bv.y;
            *reinterpret_cast<float2*>(out + (size_t)r0 * OUTDIM + c) = v0;
            *reinterpret_cast<float2*>(out + (size_t)(r0 + 8) * OUTDIM + c) = v1;
        }
    }
}

// ---------------- launch ----------------
extern "C" void kernel_launch(void* const* d_in, const int* in_sizes, int n_in,
                              void* d_out, int out_size) {
    const float* x      = (const float*)d_in[0];
    const float* weight = (const float*)d_in[1];
    const float* bias   = (const float*)d_in[2];
    const float* lora_a = (const float*)d_in[3];
    const float* lora_b = (const float*)d_in[4];
    const void*  indices = d_in[5];
    float* out = (float*)d_out;

    cudaFuncSetAttribute(gemm_kernel, cudaFuncAttributeMaxDynamicSharedMemorySize, SMEM_BYTES);

    convert_all_kernel<<<((TOKENS + OUTDIM) * KG) / 256, 256>>>(x, weight, lora_b,
                                                                (const int*)indices);
    lora_proj_kernel<<<TOKENS, 128>>>(x, lora_a, indices);
    gemm_kernel<<<(TOKENS / BM) * (OUTDIM / BN), 512, SMEM_BYTES>>>(bias, out);
}

// round 15
// speedup vs baseline: 1.0550x; 1.0074x over previous
#include <cuda_runtime.h>
#include <cuda_fp16.h>
#include <cstdint>

#define TOKENS 2048
#define HIDDEN 4096
#define OUTDIM 4096
#define NLORA  16
#define RANK   16
#define KEXT   (HIDDEN + NLORA * RANK)   // 4352
#define KG     (KEXT / 16)               // 272

#define BM 256
#define BN 128
#define BK 64
#define NCH (KEXT / BK)                  // 68

#define STRIDE 144                       // 128B data + 16B pad
#define OFF_A 0
#define OFF_B (BM * STRIDE)              // 36864
#define STG   ((BM + BN) * STRIDE)       // 55296
#define SMEM_BYTES (3 * STG)             // 165888

#define NCONV (((TOKENS + OUTDIM) * KG) / 256)   // 6528 convert blocks
static_assert(KEXT % BK == 0, "");

// unified fp16 operand buffer: x rows [0, TOKENS), w rows [TOKENS, TOKENS+OUTDIM)
__device__ __align__(16) __half g_xw[(size_t)(TOKENS + OUTDIM) * KEXT];
__device__ __align__(16) float g_ax[TOKENS][RANK];   // staged lora projections
__device__ int g_idx64;

// ---------------- helpers ----------------
__device__ __forceinline__ uint32_t smem_u32(const void* p) {
    uint32_t a;
    asm("{ .reg .u64 t; cvta.to.shared.u64 t, %1; cvt.u32.u64 %0, t; }" : "=r"(a) : "l"(p));
    return a;
}
__device__ __forceinline__ void cp16(uint32_t sdst, const void* gsrc) {
    asm volatile("cp.async.cg.shared.global [%0], [%1], 16;" :: "r"(sdst), "l"(gsrc) : "memory");
}
#define CP_COMMIT() asm volatile("cp.async.commit_group;" ::: "memory")

#define LDSM4(r, a) \
    asm volatile("ldmatrix.sync.aligned.m8n8.x4.shared.b16 {%0,%1,%2,%3}, [%4];" \
        : "=r"((r)[0]), "=r"((r)[1]), "=r"((r)[2]), "=r"((r)[3]) : "r"(a))

__device__ __forceinline__ void mma16816(float* c, const uint32_t* a, uint32_t b0, uint32_t b1) {
    asm volatile(
        "mma.sync.aligned.m16n8k16.row.col.f32.f16.f16.f32 "
        "{%0,%1,%2,%3}, {%4,%5,%6,%7}, {%8,%9}, {%0,%1,%2,%3};"
        : "+f"(c[0]), "+f"(c[1]), "+f"(c[2]), "+f"(c[3])
        : "r"(a[0]), "r"(a[1]), "r"(a[2]), "r"(a[3]), "r"(b0), "r"(b1));
}

// ---------------- fused prep ----------------
// blocks [0, TOKENS): lora rank-16 projection for token t -> g_ax (self-detect dtype)
// blocks [TOKENS, TOKENS+NCONV): x/W/lora_b -> fp16 into g_xw (ext cols of x zeroed)
__global__ void __launch_bounds__(256)
prep_kernel(const float* __restrict__ x,
            const float* __restrict__ w,
            const float* __restrict__ lb,
            const float* __restrict__ la,
            const void* __restrict__ idx_raw) {
    const int tid = threadIdx.x;

    if (blockIdx.x < TOKENS) {
        // ---- lora path ----
        const int t = blockIdx.x;
        __shared__ int any;
        if (tid == 0) any = 0;
        __syncthreads();
        const int* idx32 = (const int*)idx_raw;
        for (int i = tid * 2 + 1; i < TOKENS; i += 512)
            if (idx32[i] != 0) any = 1;
        __syncthreads();
        const int is64 = (any == 0) ? 1 : 0;
        if (t == 0 && tid == 0) g_idx64 = is64;

        int idx;
        if (is64) idx = (int)((const long long*)idx_raw)[t];
        else      idx = idx32[t];
        if (idx < 0 || idx >= NLORA) return;

        const float4* xr = reinterpret_cast<const float4*>(x + (size_t)t * HIDDEN);
        const float* A = la + (size_t)idx * RANK * HIDDEN;
        float acc[RANK];
#pragma unroll
        for (int r = 0; r < RANK; r++) acc[r] = 0.f;
        for (int j = tid; j < HIDDEN / 4; j += 256) {
            float4 xv = xr[j];
#pragma unroll
            for (int r = 0; r < RANK; r++) {
                float4 av = reinterpret_cast<const float4*>(A + (size_t)r * HIDDEN)[j];
                acc[r] += xv.x * av.x + xv.y * av.y + xv.z * av.z + xv.w * av.w;
            }
        }
#pragma unroll
        for (int r = 0; r < RANK; r++)
#pragma unroll
            for (int o = 16; o > 0; o >>= 1)
                acc[r] += __shfl_xor_sync(0xffffffffu, acc[r], o);

        __shared__ float red[8][RANK];
        int wrp = tid >> 5, l = tid & 31;
        if (l == 0)
#pragma unroll
            for (int r = 0; r < RANK; r++) red[wrp][r] = acc[r];
        __syncthreads();
        if (tid < RANK) {
            int r = tid;
            float s = 0.f;
#pragma unroll
            for (int q = 0; q < 8; q++) s += red[q][r];
            g_ax[t][r] = s;
        }
        return;
    }

    // ---- convert path ----
    int i = (int)(blockIdx.x - TOKENS) * 256 + tid;   // one 16-col group
    if (i >= (TOKENS + OUTDIM) * KG) return;
    int row = i / KG;
    int c = (i % KG) * 16;

    __half h[16];
    const float4* src = nullptr;
    if (row < TOKENS) {                               // x side
        if (c < HIDDEN) src = reinterpret_cast<const float4*>(x + (size_t)row * HIDDEN + c);
    } else {                                          // w side
        int wrow = row - TOKENS;
        if (c < HIDDEN) {
            src = reinterpret_cast<const float4*>(w + (size_t)wrow * HIDDEN + c);
        } else {
            int l = (c - HIDDEN) >> 4;                // full rank-16 row of lora l
            src = reinterpret_cast<const float4*>(lb + ((size_t)l * OUTDIM + wrow) * RANK);
        }
    }
    if (src) {
#pragma unroll
        for (int g = 0; g < 4; g++) {
            float4 v = src[g];
            h[g * 4 + 0] = __float2half(v.x); h[g * 4 + 1] = __float2half(v.y);
            h[g * 4 + 2] = __float2half(v.z); h[g * 4 + 3] = __float2half(v.w);
        }
    } else {
#pragma unroll
        for (int j = 0; j < 16; j++) h[j] = __float2half(0.f);
    }
    int4* dst = reinterpret_cast<int4*>(g_xw + (size_t)row * KEXT + c);
    dst[0] = reinterpret_cast<int4*>(h)[0];
    dst[1] = reinterpret_cast<int4*>(h)[1];
}

// ---------------- scatter staged lora projections into x ext cols ----------------
__global__ void scatter_ax_kernel(const void* __restrict__ idx_raw) {
    int t = blockIdx.x * blockDim.x + threadIdx.x;
    if (t >= TOKENS) return;
    int idx;
    if (g_idx64) idx = (int)((const long long*)idx_raw)[t];
    else         idx = ((const int*)idx_raw)[t];
    if (idx < 0 || idx >= NLORA) return;
    __half h[16];
#pragma unroll
    for (int r = 0; r < RANK; r++) h[r] = __float2half(g_ax[t][r]);
    int4* dst = reinterpret_cast<int4*>(g_xw + (size_t)t * KEXT + HIDDEN + idx * RANK);
    dst[0] = reinterpret_cast<int4*>(h)[0];
    dst[1] = reinterpret_cast<int4*>(h)[1];
}

// ---------------- main GEMM: out = x_f16 @ w_f16^T (fp32 accum) + bias ----------------
__global__ void __launch_bounds__(512, 1)
gemm_kernel(const float* __restrict__ bias, float* __restrict__ out) {
    extern __shared__ char smem[];
    const uint32_t sb = smem_u32(smem);
    const int tid = threadIdx.x;
    const int lane = tid & 31, wid = tid >> 5;
    const int wm = wid >> 2, wn = wid & 3;          // 4 x 4 warps, warp tile 64 x 32
    const int m0 = (int)(blockIdx.x & 7) * BM;
    const int n0 = (int)(blockIdx.x >> 3) * BN;

    // cp.async slots: 384 rows x 8 segs = 3072 / 512 threads = 6 each
    uint32_t goff[6], soff[6];
#pragma unroll
    for (int j = 0; j < 6; j++) {
        int s = tid + j * 512;
        int row = s >> 3, seg = s & 7;
        uint32_t loc, grow;
        if (row < 256) { grow = m0 + row;                 loc = OFF_A + row * STRIDE; }
        else           { grow = TOKENS + n0 + row - 256;  loc = OFF_B + (row - 256) * STRIDE; }
        goff[j] = grow * (uint32_t)KEXT + (uint32_t)seg * 8;
        soff[j] = loc + (uint32_t)seg * 16;
    }

    // ldmatrix lane base offsets (within a stage)
    const uint32_t a_base = (uint32_t)(wm * 64 + (lane & 15)) * STRIDE + ((lane >> 4) << 4);
    const uint32_t b_base = (uint32_t)(wn * 32 + (lane & 15)) * STRIDE + ((lane >> 4) << 4);

    float acc[4][4][4];
#pragma unroll
    for (int a = 0; a < 4; a++)
#pragma unroll
        for (int b = 0; b < 4; b++)
#pragma unroll
            for (int c = 0; c < 4; c++) acc[a][b][c] = 0.f;

    // prologue: stages 0 and 1
#pragma unroll
    for (int p = 0; p < 2; p++) {
        uint32_t s0 = sb + (uint32_t)p * STG;
#pragma unroll
        for (int j = 0; j < 6; j++)
            cp16(s0 + soff[j], g_xw + goff[j] + p * BK);
        CP_COMMIT();
    }

#pragma unroll 1
    for (int ks = 0; ks < NCH; ks++) {
        const uint32_t s0 = sb + (uint32_t)(ks % 3) * STG;
        if (ks < NCH - 1) asm volatile("cp.async.wait_group 1;" ::: "memory");
        else              asm volatile("cp.async.wait_group 0;" ::: "memory");
        __syncthreads();

        if (ks + 2 < NCH) {
            const uint32_t sl = sb + (uint32_t)((ks + 2) % 3) * STG;
            const uint32_t kadd = (uint32_t)(ks + 2) * BK;
#pragma unroll
            for (int j = 0; j < 6; j++)
                cp16(sl + soff[j], g_xw + goff[j] + kadd);
            CP_COMMIT();
        }

#pragma unroll
        for (int k16 = 0; k16 < 4; k16++) {
            const uint32_t koff = (uint32_t)k16 * 32;
            uint32_t bh[8];
            LDSM4(bh + 0, s0 + OFF_B + b_base + koff);
            LDSM4(bh + 4, s0 + OFF_B + b_base + 16 * STRIDE + koff);
#pragma unroll
            for (int mt = 0; mt < 4; mt++) {
                uint32_t ah[4];
                LDSM4(ah, s0 + OFF_A + a_base + (uint32_t)mt * 16 * STRIDE + koff);
#pragma unroll
                for (int j = 0; j < 4; j++) {
                    const int g = (j >> 1) * 4 + (j & 1);
                    mma16816(acc[mt][j], ah, bh[g], bh[g + 2]);
                }
            }
        }
    }

    // epilogue: acc + bias -> out
    const int orow = m0 + wm * 64 + (lane >> 2);
    const int ocol = n0 + wn * 32 + (lane & 3) * 2;
#pragma unroll
    for (int mt = 0; mt < 4; mt++) {
#pragma unroll
        for (int j = 0; j < 4; j++) {
            const int r0 = orow + mt * 16;
            const int c = ocol + j * 8;
            float2 bv = *reinterpret_cast<const float2*>(bias + c);
            float2 v0, v1;
            v0.x = acc[mt][j][0] + bv.x; v0.y = acc[mt][j][1] + bv.y;
            v1.x = acc[mt][j][2] + bv.x; v1.y = acc[mt][j][3] + bv.y;
            *reinterpret_cast<float2*>(out + (size_t)r0 * OUTDIM + c) = v0;
            *reinterpret_cast<float2*>(out + (size_t)(r0 + 8) * OUTDIM + c) = v1;
        }
    }
}

// ---------------- launch ----------------
extern "C" void kernel_launch(void* const* d_in, const int* in_sizes, int n_in,
                              void* d_out, int out_size) {
    const float* x      = (const float*)d_in[0];
    const float* weight = (const float*)d_in[1];
    const float* bias   = (const float*)d_in[2];
    const float* lora_a = (const float*)d_in[3];
    const float* lora_b = (const float*)d_in[4];
    const void*  indices = d_in[5];
    float* out = (float*)d_out;

    cudaFuncSetAttribute(gemm_kernel, cudaFuncAttributeMaxDynamicSharedMemorySize, SMEM_BYTES);

    prep_kernel<<<TOKENS + NCONV, 256>>>(x, weight, lora_b, lora_a, indices);
    scatter_ax_kernel<<<TOKENS / 256, 256>>>(indices);
    gemm_kernel<<<(TOKENS / BM) * (OUTDIM / BN), 512, SMEM_BYTES>>>(bias, out);
}